// round 9
// baseline (speedup 1.0000x reference)
#include <cuda_runtime.h>
#include <cuda_bf16.h>
#include <cstdint>
#include <cstddef>

// Problem dims
#define BD 512      // batch
#define HD 1024     // hidden
#define OD 256      // output dim
#define TT 128      // target length
#define ND 4096     // 4*HD gate columns (blocked: col = (j>>3)*32 + gate*8 + (j&7))

// ---------------- GEMM config: BK=64, 3-stage ring ----------------
#define BK 64
#define GP 68                          // smem pitch in floats (conflict-free frag loads)
#define GSTG (128 * GP)                // one stage of one operand
#define GEMM_SMEM (3 * 2 * GSTG * 4)   // 208896 B

// single dynamic-shared declaration for the whole TU
extern __shared__ float dynsmem[];

// ---------------- scratch (device globals) ----------------
// K-axis interleave: within each 32-chunk, logical k stored at (k&3)*8 + (k>>2).
__device__ __align__(16) float g_Wg0t[(size_t)ND * HD];    // [n][k'] W_hh part (tf32)
__device__ __align__(16) float g_Wgt [(size_t)ND * HD];    // [n][k'] folded weight (tf32)
__device__ __align__(16) float g_WihI[(size_t)ND * OD];    // [n][o'] W_ih (tf32)
__device__ __align__(16) float g_WoutR[(size_t)OD * HD];   // [o][k'] Wout (tf32)
__device__ __align__(16) float g_WoutT[(size_t)HD * OD];   // [k][o'] Wout^T (tf32)
__device__ __align__(16) float g_b0[ND];
__device__ __align__(16) float g_bg[ND];
__device__ __align__(16) float g_h0[(size_t)BD * HD];      // [b][k'] tf32
__device__ __align__(16) float g_H [(size_t)TT * BD * HD]; // [t][b][k'] tf32
__device__ unsigned g_barCnt;
__device__ unsigned g_barEpoch;

// ---------------- helpers ----------------
__device__ __forceinline__ int permK(int k) {
    return (k & ~31) + ((k & 3) << 3) + ((k >> 2) & 7);
}
__device__ __forceinline__ float to_tf32(float x) {
    unsigned u;
    asm("cvt.rna.tf32.f32 %0, %1;" : "=r"(u) : "f"(x));
    return __uint_as_float(u);
}
__device__ __forceinline__ float fsigmoid(float x) { return 1.0f / (1.0f + __expf(-x)); }
__device__ __forceinline__ float ftanh(float x) {
    float e = __expf(2.0f * x);
    return 1.0f - 2.0f / (e + 1.0f);
}
__device__ __forceinline__ void cp_a16(float* d, const float* s) {
    unsigned a = (unsigned)__cvta_generic_to_shared(d);
    asm volatile("cp.async.cg.shared.global [%0], [%1], 16;" :: "r"(a), "l"(s));
}

// ---------------- mma.sync mainloop: C(128x128) += A(128xK) * B(128xK)^T ----------------
// A stored [row][k'] (lda), B stored [col][k'] (ldb), both K-interleaved.
__device__ __forceinline__ void gemm_tile(
    const float* __restrict__ A, int lda,
    const float* __restrict__ B, int ldb,
    int m0, int n0, int kTiles,
    float (&acc)[4][4][4], float* sm)
{
    float* sA = sm;
    float* sB = sm + 3 * GSTG;
    const int tid = threadIdx.x;
    const int lane = tid & 31;
    const int wid = tid >> 5;
    const int wm = wid & 1, wn = wid >> 1;
    const int gid = lane >> 2, tig = lane & 3;

#define LOAD_STAGE(s, k0) do { \
        float* dA = sA + (s) * GSTG; \
        float* dB = sB + (s) * GSTG; \
        _Pragma("unroll") \
        for (int i = 0; i < 8; ++i) { \
            int slot = tid + i * 256; \
            int r = slot >> 4, cc = slot & 15; \
            cp_a16(dA + r * GP + cc * 4, A + (size_t)(m0 + r) * lda + (k0) + cc * 4); \
        } \
        _Pragma("unroll") \
        for (int i = 0; i < 8; ++i) { \
            int slot = tid + i * 256; \
            int r = slot >> 4, cc = slot & 15; \
            cp_a16(dB + r * GP + cc * 4, B + (size_t)(n0 + r) * ldb + (k0) + cc * 4); \
        } \
        asm volatile("cp.async.commit_group;" ::: "memory"); \
    } while (0)

    LOAD_STAGE(0, 0);
    LOAD_STAGE(1, BK);

    int cs = 0;        // compute stage
    int ls = 2;        // next load stage slot
    for (int kt = 0; kt < kTiles; ++kt) {
        if (kt + 1 < kTiles) asm volatile("cp.async.wait_group 1;" ::: "memory");
        else                 asm volatile("cp.async.wait_group 0;" ::: "memory");
        __syncthreads();
        if (kt + 2 < kTiles) {
            LOAD_STAGE(ls, (kt + 2) * BK);
            ls = (ls + 1 == 3) ? 0 : ls + 1;
        }

        const float* cA = sA + cs * GSTG;
        const float* cB = sB + cs * GSTG;
        cs = (cs + 1 == 3) ? 0 : cs + 1;

        #pragma unroll
        for (int c2 = 0; c2 < 2; ++c2) {
            #pragma unroll
            for (int h2 = 0; h2 < 2; ++h2) {
                const int off = c2 * 32 + tig * 8 + h2 * 4;
                float aw[8][4];
                float bw[4][4];
                #pragma unroll
                for (int mf = 0; mf < 4; ++mf)
                    #pragma unroll
                    for (int rh = 0; rh < 2; ++rh) {
                        int r = wm * 64 + mf * 16 + gid + rh * 8;
                        *(float4*)aw[mf * 2 + rh] = *(const float4*)&cA[r * GP + off];
                    }
                #pragma unroll
                for (int nf = 0; nf < 4; ++nf) {
                    int r = wn * 32 + nf * 8 + gid;
                    *(float4*)bw[nf] = *(const float4*)&cB[r * GP + off];
                }
                #pragma unroll
                for (int ks2 = 0; ks2 < 2; ++ks2) {
                    #pragma unroll
                    for (int mf = 0; mf < 4; ++mf) {
                        unsigned a0 = __float_as_uint(aw[mf * 2][2 * ks2]);
                        unsigned a1 = __float_as_uint(aw[mf * 2 + 1][2 * ks2]);
                        unsigned a2 = __float_as_uint(aw[mf * 2][2 * ks2 + 1]);
                        unsigned a3 = __float_as_uint(aw[mf * 2 + 1][2 * ks2 + 1]);
                        #pragma unroll
                        for (int nf = 0; nf < 4; ++nf) {
                            unsigned b0 = __float_as_uint(bw[nf][2 * ks2]);
                            unsigned b1 = __float_as_uint(bw[nf][2 * ks2 + 1]);
                            asm volatile(
                                "mma.sync.aligned.m16n8k8.row.col.f32.tf32.tf32.f32 "
                                "{%0,%1,%2,%3}, {%4,%5,%6,%7}, {%8,%9}, {%0,%1,%2,%3};"
                                : "+f"(acc[mf][nf][0]), "+f"(acc[mf][nf][1]),
                                  "+f"(acc[mf][nf][2]), "+f"(acc[mf][nf][3])
                                : "r"(a0), "r"(a1), "r"(a2), "r"(a3), "r"(b0), "r"(b1));
                        }
                    }
                }
            }
        }
    }
#undef LOAD_STAGE
}

// ---------------- setup kernels ----------------
// Column layout: n = (j>>3)*32 + g*8 + (j&7)  ->  j = ((n>>5)<<3)|(n&7), g = (n>>3)&3
__global__ void k_build_all(const float* __restrict__ Whh,
                            const float* __restrict__ Wih,
                            const float* __restrict__ Wout) {
    size_t idx = (size_t)blockIdx.x * blockDim.x + threadIdx.x;
    if (idx < (size_t)ND * HD) {
        int n = (int)(idx >> 10);
        int k = (int)(idx & (HD - 1));
        int j = ((n >> 5) << 3) | (n & 7), g = (n >> 3) & 3;
        g_Wg0t[(size_t)n * HD + permK(k)] = to_tf32(Whh[(size_t)(g * HD + j) * HD + k]);
    }
    if (idx < (size_t)ND * OD) {
        int n = (int)(idx >> 8);
        int o = (int)(idx & (OD - 1));
        int j = ((n >> 5) << 3) | (n & 7), g = (n >> 3) & 3;
        g_WihI[(size_t)n * OD + permK(o)] = to_tf32(Wih[(size_t)(g * HD + j) * OD + o]);
    }
    if (idx < (size_t)OD * HD) {
        int o = (int)(idx >> 10);
        int k = (int)(idx & (HD - 1));
        float v = to_tf32(Wout[idx]);
        g_WoutR[(size_t)o * HD + permK(k)] = v;   // [o][k']
        g_WoutT[(size_t)k * OD + permK(o)] = v;   // [k][o']
    }
}
__global__ void k_h0(const float* __restrict__ enc) {
    size_t idx = (size_t)blockIdx.x * blockDim.x + threadIdx.x;
    if (idx >= (size_t)BD * HD) return;
    int b = (int)(idx >> 10);
    int k = (int)(idx & (HD - 1));
    g_h0[(size_t)b * HD + permK(k)] = to_tf32(enc[idx]);
}
__global__ void k_bias(const float* __restrict__ Wih, const float* __restrict__ bih,
                       const float* __restrict__ bhh, const float* __restrict__ bout) {
    int warp = (blockIdx.x * blockDim.x + threadIdx.x) >> 5;
    int lane = threadIdx.x & 31;
    if (warp >= ND) return;
    int n = warp;
    int j = ((n >> 5) << 3) | (n & 7), g = (n >> 3) & 3;
    int np = g * HD + j;
    float acc = 0.f;
    const float* wr = Wih + (size_t)np * OD;
    for (int o = lane; o < OD; o += 32) acc += wr[o] * bout[o];
    #pragma unroll
    for (int off = 16; off; off >>= 1) acc += __shfl_xor_sync(0xFFFFFFFFu, acc, off);
    if (lane == 0) {
        float b0 = bih[np] + bhh[np];
        g_b0[n] = b0;
        g_bg[n] = b0 + acc;
    }
}
__global__ void k_reset() {
    g_barCnt = 0;
    g_barEpoch = 0;
}
// Wgt[n][k'] = tf32( Wg0t[n][k'] + (Wih*Wout)[np][k] )
__global__ __launch_bounds__(256, 1) void k_build_Wgt() {
    float* smem = dynsmem;
    const int m0 = blockIdx.y * 128;   // gate rows
    const int n0 = blockIdx.x * 128;   // k cols (logical)
    float acc[4][4][4];
    #pragma unroll
    for (int a = 0; a < 4; ++a)
        #pragma unroll
        for (int b = 0; b < 4; ++b)
            #pragma unroll
            for (int c = 0; c < 4; ++c) acc[a][b][c] = 0.f;
    gemm_tile(g_WihI, OD, g_WoutT, OD, m0, n0, OD / BK, acc, smem);

    const int tid = threadIdx.x, lane = tid & 31, wid = tid >> 5;
    const int wm = wid & 1, wn = wid >> 1, gid = lane >> 2, tig = lane & 3;
    #pragma unroll
    for (int mf = 0; mf < 4; ++mf)
        #pragma unroll
        for (int nf = 0; nf < 4; ++nf) {
            int c0 = n0 + wn * 32 + nf * 8 + 2 * tig;
            #pragma unroll
            for (int half = 0; half < 2; ++half) {
                int row = m0 + wm * 64 + mf * 16 + gid + half * 8;
                #pragma unroll
                for (int dd = 0; dd < 2; ++dd) {
                    size_t p = (size_t)row * HD + permK(c0 + dd);
                    g_Wgt[p] = to_tf32(g_Wg0t[p] + acc[mf][nf][half * 2 + dd]);
                }
            }
        }
}

// ---------------- persistent recurrence kernel: all 128 steps, one launch ----------------
__global__ __launch_bounds__(256, 1) void k_persist() {
    float* smem = dynsmem;
    const int tid = threadIdx.x, lane = tid & 31, wid = tid >> 5;
    const int wm = wid & 1, wn = wid >> 1, gid = lane >> 2, tig = lane & 3;
    const int n0 = blockIdx.x * 128;   // gate cols
    const int m0 = blockIdx.y * 128;   // batch rows
    const unsigned nCta = gridDim.x * gridDim.y;

    // per-thread epilogue geometry (fixed across steps)
    const int nb = n0 + wn * 32;
    const int jb = nb >> 2;
    const int ub = 2 * tig;
    int hofs[4][2][2];                 // offset into a (BD*HD) h-plane
    #pragma unroll
    for (int mf = 0; mf < 4; ++mf)
        #pragma unroll
        for (int half = 0; half < 2; ++half) {
            const int row = m0 + wm * 64 + mf * 16 + gid + half * 8;
            #pragma unroll
            for (int uu = 0; uu < 2; ++uu)
                hofs[mf][half][uu] = row * HD + permK(jb + ub + uu);
        }

    // biases in registers
    float rbI[2], rbF[2], rbG[2], rbO[2];
    float rb0I[2], rb0F[2], rb0G[2], rb0O[2];
    #pragma unroll
    for (int uu = 0; uu < 2; ++uu) {
        rbI[uu] = g_bg[nb +       ub + uu];  rb0I[uu] = g_b0[nb +       ub + uu];
        rbF[uu] = g_bg[nb +  8 +  ub + uu];  rb0F[uu] = g_b0[nb +  8 +  ub + uu];
        rbG[uu] = g_bg[nb + 16 +  ub + uu];  rb0G[uu] = g_b0[nb + 16 +  ub + uu];
        rbO[uu] = g_bg[nb + 24 +  ub + uu];  rb0O[uu] = g_b0[nb + 24 +  ub + uu];
    }

    // cell state lives in registers for the whole run
    float cst[4][2][2];
    #pragma unroll
    for (int mf = 0; mf < 4; ++mf)
        #pragma unroll
        for (int half = 0; half < 2; ++half)
            #pragma unroll
            for (int uu = 0; uu < 2; ++uu) cst[mf][half][uu] = 0.f;

    unsigned epoch = 0;
    #pragma unroll 1
    for (int t = 0; t < TT; ++t) {
        const float* A = (t == 0) ? g_h0 : (g_H + (size_t)(t - 1) * BD * HD);
        const float* W = (t == 0) ? g_Wg0t : g_Wgt;
        float* hout = g_H + (size_t)t * BD * HD;

        float acc[4][4][4];
        #pragma unroll
        for (int a = 0; a < 4; ++a)
            #pragma unroll
            for (int b = 0; b < 4; ++b)
                #pragma unroll
                for (int c = 0; c < 4; ++c) acc[a][b][c] = 0.f;
        gemm_tile(A, HD, W, HD, m0, n0, HD / BK, acc, smem);

        // LSTM cell epilogue, fully in registers
        #pragma unroll
        for (int mf = 0; mf < 4; ++mf)
            #pragma unroll
            for (int half = 0; half < 2; ++half)
                #pragma unroll
                for (int uu = 0; uu < 2; ++uu) {
                    float bi = (t == 0) ? rb0I[uu] : rbI[uu];
                    float bf = (t == 0) ? rb0F[uu] : rbF[uu];
                    float bg = (t == 0) ? rb0G[uu] : rbG[uu];
                    float bo = (t == 0) ? rb0O[uu] : rbO[uu];
                    float ig = fsigmoid(acc[mf][0][half * 2 + uu] + bi);
                    float fg = fsigmoid(acc[mf][1][half * 2 + uu] + bf);
                    float gg = ftanh  (acc[mf][2][half * 2 + uu] + bg);
                    float og = fsigmoid(acc[mf][3][half * 2 + uu] + bo);
                    float cn = fg * cst[mf][half][uu] + ig * gg;
                    cst[mf][half][uu] = cn;
                    hout[hofs[mf][half][uu]] = to_tf32(og * ftanh(cn));
                }

        // global barrier (epoch-based; counters reset by k_reset each launch)
        __threadfence();
        __syncthreads();
        if (tid == 0) {
            unsigned e = atomicAdd(&g_barCnt, 1u);
            if (e == nCta - 1) {
                atomicExch(&g_barCnt, 0u);
                __threadfence();
                atomicAdd(&g_barEpoch, 1u);
            } else {
                while (*(volatile unsigned*)&g_barEpoch <= epoch) { }
            }
            __threadfence();
        }
        ++epoch;
        __syncthreads();
    }
}

// ---------------- final prediction GEMM: (T*B, O) = H_all @ Wout^T + b_out ----------------
__global__ __launch_bounds__(256, 1) void k_pred(const float* __restrict__ bout,
                                                 float* __restrict__ out) {
    float* smem = dynsmem;
    const int m0 = blockIdx.y * 128;
    const int n0 = blockIdx.x * 128;
    float acc[4][4][4];
    #pragma unroll
    for (int a = 0; a < 4; ++a)
        #pragma unroll
        for (int b = 0; b < 4; ++b)
            #pragma unroll
            for (int c = 0; c < 4; ++c) acc[a][b][c] = 0.f;
    gemm_tile(g_H, HD, g_WoutR, HD, m0, n0, HD / BK, acc, smem);

    const int tid = threadIdx.x, lane = tid & 31, wid = tid >> 5;
    const int wm = wid & 1, wn = wid >> 1, gid = lane >> 2, tig = lane & 3;
    #pragma unroll
    for (int mf = 0; mf < 4; ++mf)
        #pragma unroll
        for (int nf = 0; nf < 4; ++nf) {
            int c = wn * 32 + nf * 8 + 2 * tig;
            int o = n0 + c;
            float b0v = bout[o], b1v = bout[o + 1];
            #pragma unroll
            for (int half = 0; half < 2; ++half) {
                int m = m0 + wm * 64 + mf * 16 + gid + half * 8;
                int t = m >> 9;
                int b = m & 511;
                float2 v;
                v.x = acc[mf][nf][half * 2 + 0] + b0v;
                v.y = acc[mf][nf][half * 2 + 1] + b1v;
                *(float2*)&out[((size_t)b * TT + t) * OD + o] = v;
            }
        }
}

// ---------------- host launcher ----------------
extern "C" void kernel_launch(void* const* d_in, const int* in_sizes, int n_in,
                              void* d_out, int out_size) {
    const float* enc  = (const float*)d_in[0];
    const float* Wih  = (const float*)d_in[2];
    const float* Whh  = (const float*)d_in[3];
    const float* bih  = (const float*)d_in[4];
    const float* bhh  = (const float*)d_in[5];
    const float* Wout = (const float*)d_in[6];
    const float* bout = (const float*)d_in[7];
    float* out = (float*)d_out;

    cudaFuncSetAttribute(k_build_Wgt, cudaFuncAttributeMaxDynamicSharedMemorySize, GEMM_SMEM);
    cudaFuncSetAttribute(k_persist,   cudaFuncAttributeMaxDynamicSharedMemorySize, GEMM_SMEM);
    cudaFuncSetAttribute(k_pred,      cudaFuncAttributeMaxDynamicSharedMemorySize, GEMM_SMEM);

    // launch order chosen so ncu (-s 5 -c 1) captures k_persist (launch #6)
    k_build_all<<<(ND * HD + 255) / 256, 256>>>(Whh, Wih, Wout);   // 1
    k_h0       <<<(BD * HD + 255) / 256, 256>>>(enc);              // 2
    k_bias     <<<(ND * 32 + 255) / 256, 256>>>(Wih, bih, bhh, bout); // 3
    k_reset    <<<1, 1>>>();                                       // 4
    {
        dim3 g(HD / 128, ND / 128);        // 8 x 32
        k_build_Wgt<<<g, 256, GEMM_SMEM>>>();                      // 5
    }
    {
        dim3 g(ND / 128, BD / 128);        // 32 x 4 = 128 CTAs (single wave)
        k_persist<<<g, 256, GEMM_SMEM>>>();                        // 6
    }
    {
        dim3 g(OD / 128, (TT * BD) / 128); // 2 x 512
        k_pred<<<g, 256, GEMM_SMEM>>>(bout, out);                  // 7
    }
}

// round 10
// speedup vs baseline: 1.5931x; 1.5931x over previous
#include <cuda_runtime.h>
#include <cuda_bf16.h>
#include <cstdint>
#include <cstddef>

// Problem dims
#define BD 512      // batch
#define HD 1024     // hidden
#define OD 256      // output dim
#define TT 128      // target length
#define ND 4096     // 4*HD gate columns (blocked: col = (j>>3)*32 + gate*8 + (j&7))

// ---------------- GEMM config: BK=64, 3-stage ring ----------------
#define BK 64
#define GP 68                          // smem pitch in floats (conflict-free frag loads)
#define GSTG (128 * GP)                // one stage of one operand
#define GEMM_SMEM (3 * 2 * GSTG * 4)   // 208896 B
#define CST_FLOATS (16 * 256)          // per-CTA cell-state area
#define PERSIST_SMEM (GEMM_SMEM + CST_FLOATS * 4)   // 225280 B

// single dynamic-shared declaration for the whole TU
extern __shared__ float dynsmem[];

// ---------------- scratch (device globals) ----------------
// K-axis interleave: within each 32-chunk, logical k stored at (k&3)*8 + (k>>2).
__device__ __align__(16) float g_Wg0t[(size_t)ND * HD];    // [n][k'] W_hh part (tf32)
__device__ __align__(16) float g_Wgt [(size_t)ND * HD];    // [n][k'] folded weight (tf32)
__device__ __align__(16) float g_WihI[(size_t)ND * OD];    // [n][o'] W_ih (tf32)
__device__ __align__(16) float g_WoutR[(size_t)OD * HD];   // [o][k'] Wout (tf32)
__device__ __align__(16) float g_WoutT[(size_t)HD * OD];   // [k][o'] Wout^T (tf32)
__device__ __align__(16) float g_b0[ND];
__device__ __align__(16) float g_bg[ND];
__device__ __align__(16) float g_h0[(size_t)BD * HD];      // [b][k'] tf32
__device__ __align__(16) float g_H [(size_t)TT * BD * HD]; // [t][b][k'] tf32
__device__ unsigned g_barCnt;
__device__ unsigned g_barEpoch;

// ---------------- helpers ----------------
__device__ __forceinline__ int permK(int k) {
    return (k & ~31) + ((k & 3) << 3) + ((k >> 2) & 7);
}
__device__ __forceinline__ float to_tf32(float x) {
    unsigned u;
    asm("cvt.rna.tf32.f32 %0, %1;" : "=r"(u) : "f"(x));
    return __uint_as_float(u);
}
__device__ __forceinline__ float fsigmoid(float x) { return 1.0f / (1.0f + __expf(-x)); }
__device__ __forceinline__ float ftanh(float x) {
    float e = __expf(2.0f * x);
    return 1.0f - 2.0f / (e + 1.0f);
}
__device__ __forceinline__ void cp_a16(float* d, const float* s) {
    unsigned a = (unsigned)__cvta_generic_to_shared(d);
    asm volatile("cp.async.cg.shared.global [%0], [%1], 16;" :: "r"(a), "l"(s));
}

// ---------------- mma.sync mainloop: C(128x128) += A(128xK) * B(128xK)^T ----------------
// A stored [row][k'] (lda), B stored [col][k'] (ldb), both K-interleaved.
__device__ __forceinline__ void gemm_tile(
    const float* __restrict__ A, int lda,
    const float* __restrict__ B, int ldb,
    int m0, int n0, int kTiles,
    float (&acc)[4][4][4], float* sm)
{
    float* sA = sm;
    float* sB = sm + 3 * GSTG;
    const int tid = threadIdx.x;
    const int lane = tid & 31;
    const int wid = tid >> 5;
    const int wm = wid & 1, wn = wid >> 1;
    const int gid = lane >> 2, tig = lane & 3;

#define LOAD_STAGE(s, k0) do { \
        float* dA = sA + (s) * GSTG; \
        float* dB = sB + (s) * GSTG; \
        _Pragma("unroll") \
        for (int i = 0; i < 8; ++i) { \
            int slot = tid + i * 256; \
            int r = slot >> 4, cc = slot & 15; \
            cp_a16(dA + r * GP + cc * 4, A + (size_t)(m0 + r) * lda + (k0) + cc * 4); \
        } \
        _Pragma("unroll") \
        for (int i = 0; i < 8; ++i) { \
            int slot = tid + i * 256; \
            int r = slot >> 4, cc = slot & 15; \
            cp_a16(dB + r * GP + cc * 4, B + (size_t)(n0 + r) * ldb + (k0) + cc * 4); \
        } \
        asm volatile("cp.async.commit_group;" ::: "memory"); \
    } while (0)

    LOAD_STAGE(0, 0);
    LOAD_STAGE(1, BK);

    int cs = 0;        // compute stage
    int ls = 2;        // next load stage slot
    for (int kt = 0; kt < kTiles; ++kt) {
        if (kt + 1 < kTiles) asm volatile("cp.async.wait_group 1;" ::: "memory");
        else                 asm volatile("cp.async.wait_group 0;" ::: "memory");
        __syncthreads();
        if (kt + 2 < kTiles) {
            LOAD_STAGE(ls, (kt + 2) * BK);
            ls = (ls + 1 == 3) ? 0 : ls + 1;
        }

        const float* cA = sA + cs * GSTG;
        const float* cB = sB + cs * GSTG;
        cs = (cs + 1 == 3) ? 0 : cs + 1;

        #pragma unroll
        for (int c2 = 0; c2 < 2; ++c2) {
            #pragma unroll
            for (int h2 = 0; h2 < 2; ++h2) {
                const int off = c2 * 32 + tig * 8 + h2 * 4;
                float aw[8][4];
                float bw[4][4];
                #pragma unroll
                for (int mf = 0; mf < 4; ++mf)
                    #pragma unroll
                    for (int rh = 0; rh < 2; ++rh) {
                        int r = wm * 64 + mf * 16 + gid + rh * 8;
                        *(float4*)aw[mf * 2 + rh] = *(const float4*)&cA[r * GP + off];
                    }
                #pragma unroll
                for (int nf = 0; nf < 4; ++nf) {
                    int r = wn * 32 + nf * 8 + gid;
                    *(float4*)bw[nf] = *(const float4*)&cB[r * GP + off];
                }
                #pragma unroll
                for (int ks2 = 0; ks2 < 2; ++ks2) {
                    #pragma unroll
                    for (int mf = 0; mf < 4; ++mf) {
                        unsigned a0 = __float_as_uint(aw[mf * 2][2 * ks2]);
                        unsigned a1 = __float_as_uint(aw[mf * 2 + 1][2 * ks2]);
                        unsigned a2 = __float_as_uint(aw[mf * 2][2 * ks2 + 1]);
                        unsigned a3 = __float_as_uint(aw[mf * 2 + 1][2 * ks2 + 1]);
                        #pragma unroll
                        for (int nf = 0; nf < 4; ++nf) {
                            unsigned b0 = __float_as_uint(bw[nf][2 * ks2]);
                            unsigned b1 = __float_as_uint(bw[nf][2 * ks2 + 1]);
                            asm volatile(
                                "mma.sync.aligned.m16n8k8.row.col.f32.tf32.tf32.f32 "
                                "{%0,%1,%2,%3}, {%4,%5,%6,%7}, {%8,%9}, {%0,%1,%2,%3};"
                                : "+f"(acc[mf][nf][0]), "+f"(acc[mf][nf][1]),
                                  "+f"(acc[mf][nf][2]), "+f"(acc[mf][nf][3])
                                : "r"(a0), "r"(a1), "r"(a2), "r"(a3), "r"(b0), "r"(b1));
                        }
                    }
                }
            }
        }
    }
#undef LOAD_STAGE
}

// ---------------- setup kernels ----------------
// Column layout: n = (j>>3)*32 + g*8 + (j&7)  ->  j = ((n>>5)<<3)|(n&7), g = (n>>3)&3
__global__ void k_build_all(const float* __restrict__ Whh,
                            const float* __restrict__ Wih,
                            const float* __restrict__ Wout,
                            const float* __restrict__ enc) {
    size_t idx = (size_t)blockIdx.x * blockDim.x + threadIdx.x;
    if (idx < (size_t)ND * HD) {
        int n = (int)(idx >> 10);
        int k = (int)(idx & (HD - 1));
        int j = ((n >> 5) << 3) | (n & 7), g = (n >> 3) & 3;
        g_Wg0t[(size_t)n * HD + permK(k)] = to_tf32(Whh[(size_t)(g * HD + j) * HD + k]);
    }
    if (idx < (size_t)ND * OD) {
        int n = (int)(idx >> 8);
        int o = (int)(idx & (OD - 1));
        int j = ((n >> 5) << 3) | (n & 7), g = (n >> 3) & 3;
        g_WihI[(size_t)n * OD + permK(o)] = to_tf32(Wih[(size_t)(g * HD + j) * OD + o]);
    }
    if (idx < (size_t)OD * HD) {
        int o = (int)(idx >> 10);
        int k = (int)(idx & (HD - 1));
        float v = to_tf32(Wout[idx]);
        g_WoutR[(size_t)o * HD + permK(k)] = v;   // [o][k']
        g_WoutT[(size_t)k * OD + permK(o)] = v;   // [k][o']
    }
    if (idx < (size_t)BD * HD) {
        int b = (int)(idx >> 10);
        int k = (int)(idx & (HD - 1));
        g_h0[(size_t)b * HD + permK(k)] = to_tf32(enc[idx]);
    }
}
__global__ void k_bias(const float* __restrict__ Wih, const float* __restrict__ bih,
                       const float* __restrict__ bhh, const float* __restrict__ bout) {
    if (blockIdx.x == 0 && threadIdx.x == 0) {   // fold barrier reset into this launch
        g_barCnt = 0;
        g_barEpoch = 0;
    }
    int warp = (blockIdx.x * blockDim.x + threadIdx.x) >> 5;
    int lane = threadIdx.x & 31;
    if (warp >= ND) return;
    int n = warp;
    int j = ((n >> 5) << 3) | (n & 7), g = (n >> 3) & 3;
    int np = g * HD + j;
    float acc = 0.f;
    const float* wr = Wih + (size_t)np * OD;
    for (int o = lane; o < OD; o += 32) acc += wr[o] * bout[o];
    #pragma unroll
    for (int off = 16; off; off >>= 1) acc += __shfl_xor_sync(0xFFFFFFFFu, acc, off);
    if (lane == 0) {
        float b0 = bih[np] + bhh[np];
        g_b0[n] = b0;
        g_bg[n] = b0 + acc;
    }
}
// Wgt[n][k'] = tf32( Wg0t[n][k'] + (Wih*Wout)[np][k] )
__global__ __launch_bounds__(256, 1) void k_build_Wgt() {
    float* smem = dynsmem;
    const int m0 = blockIdx.y * 128;   // gate rows
    const int n0 = blockIdx.x * 128;   // k cols (logical)
    float acc[4][4][4];
    #pragma unroll
    for (int a = 0; a < 4; ++a)
        #pragma unroll
        for (int b = 0; b < 4; ++b)
            #pragma unroll
            for (int c = 0; c < 4; ++c) acc[a][b][c] = 0.f;
    gemm_tile(g_WihI, OD, g_WoutT, OD, m0, n0, OD / BK, acc, smem);

    const int tid = threadIdx.x, lane = tid & 31, wid = tid >> 5;
    const int wm = wid & 1, wn = wid >> 1, gid = lane >> 2, tig = lane & 3;
    #pragma unroll
    for (int mf = 0; mf < 4; ++mf)
        #pragma unroll
        for (int nf = 0; nf < 4; ++nf) {
            int c0 = n0 + wn * 32 + nf * 8 + 2 * tig;
            #pragma unroll
            for (int half = 0; half < 2; ++half) {
                int row = m0 + wm * 64 + mf * 16 + gid + half * 8;
                #pragma unroll
                for (int dd = 0; dd < 2; ++dd) {
                    size_t p = (size_t)row * HD + permK(c0 + dd);
                    g_Wgt[p] = to_tf32(g_Wg0t[p] + acc[mf][nf][half * 2 + dd]);
                }
            }
        }
}

// ---------------- persistent recurrence kernel: all 128 steps, one launch ----------------
// All step-persistent state lives in SMEM/global, NOT registers (R9 spilled).
__global__ __launch_bounds__(256, 1) void k_persist() {
    float* smem = dynsmem;
    float* cstS = dynsmem + 6 * GSTG;   // [16][256] cell state, conflict-free
    const int tid = threadIdx.x, lane = tid & 31, wid = tid >> 5;
    const int wm = wid & 1, wn = wid >> 1, gid = lane >> 2, tig = lane & 3;
    const int n0 = blockIdx.x * 128;   // gate cols
    const int m0 = blockIdx.y * 128;   // batch rows
    const unsigned nCta = gridDim.x * gridDim.y;

    #pragma unroll
    for (int i = 0; i < 16; ++i) cstS[i * 256 + tid] = 0.f;
    // no __syncthreads needed: each thread only touches its own slots

    unsigned epoch = 0;
    #pragma unroll 1
    for (int t = 0; t < TT; ++t) {
        const float* A = (t == 0) ? g_h0 : (g_H + (size_t)(t - 1) * BD * HD);
        const float* W = (t == 0) ? g_Wg0t : g_Wgt;
        const float* bias = (t == 0) ? g_b0 : g_bg;
        float* hout = g_H + (size_t)t * BD * HD;

        float acc[4][4][4];
        #pragma unroll
        for (int a = 0; a < 4; ++a)
            #pragma unroll
            for (int b = 0; b < 4; ++b)
                #pragma unroll
                for (int c = 0; c < 4; ++c) acc[a][b][c] = 0.f;
        gemm_tile(A, HD, W, HD, m0, n0, HD / BK, acc, smem);

        // LSTM cell epilogue; offsets recomputed, biases from global (L1-hot)
        const int nb = n0 + wn * 32;
        const int jb = nb >> 2;
        const int ub = 2 * tig;
        float bI[2], bF[2], bG[2], bO[2];
        #pragma unroll
        for (int uu = 0; uu < 2; ++uu) {
            bI[uu] = bias[nb +       ub + uu];
            bF[uu] = bias[nb +  8 +  ub + uu];
            bG[uu] = bias[nb + 16 +  ub + uu];
            bO[uu] = bias[nb + 24 +  ub + uu];
        }
        #pragma unroll
        for (int mf = 0; mf < 4; ++mf)
            #pragma unroll
            for (int half = 0; half < 2; ++half) {
                const int row = m0 + wm * 64 + mf * 16 + gid + half * 8;
                #pragma unroll
                for (int uu = 0; uu < 2; ++uu) {
                    const int ci = ((mf * 2 + half) * 2 + uu) * 256 + tid;
                    float ig = fsigmoid(acc[mf][0][half * 2 + uu] + bI[uu]);
                    float fg = fsigmoid(acc[mf][1][half * 2 + uu] + bF[uu]);
                    float gg = ftanh  (acc[mf][2][half * 2 + uu] + bG[uu]);
                    float og = fsigmoid(acc[mf][3][half * 2 + uu] + bO[uu]);
                    float cn = fg * cstS[ci] + ig * gg;
                    cstS[ci] = cn;
                    hout[row * HD + permK(jb + ub + uu)] = to_tf32(og * ftanh(cn));
                }
            }

        // global epoch barrier (counters reset in k_bias each launch)
        __threadfence();
        __syncthreads();
        if (tid == 0) {
            unsigned e = atomicAdd(&g_barCnt, 1u);
            if (e == nCta - 1) {
                g_barCnt = 0;
                __threadfence();
                atomicAdd(&g_barEpoch, 1u);
            } else {
                while (*(volatile unsigned*)&g_barEpoch <= epoch) { }
            }
            __threadfence();
        }
        ++epoch;
        __syncthreads();
    }
}

// ---------------- final prediction GEMM: (T*B, O) = H_all @ Wout^T + b_out ----------------
__global__ __launch_bounds__(256, 1) void k_pred(const float* __restrict__ bout,
                                                 float* __restrict__ out) {
    float* smem = dynsmem;
    const int m0 = blockIdx.y * 128;
    const int n0 = blockIdx.x * 128;
    float acc[4][4][4];
    #pragma unroll
    for (int a = 0; a < 4; ++a)
        #pragma unroll
        for (int b = 0; b < 4; ++b)
            #pragma unroll
            for (int c = 0; c < 4; ++c) acc[a][b][c] = 0.f;
    gemm_tile(g_H, HD, g_WoutR, HD, m0, n0, HD / BK, acc, smem);

    const int tid = threadIdx.x, lane = tid & 31, wid = tid >> 5;
    const int wm = wid & 1, wn = wid >> 1, gid = lane >> 2, tig = lane & 3;
    #pragma unroll
    for (int mf = 0; mf < 4; ++mf)
        #pragma unroll
        for (int nf = 0; nf < 4; ++nf) {
            int c = wn * 32 + nf * 8 + 2 * tig;
            int o = n0 + c;
            float b0v = bout[o], b1v = bout[o + 1];
            #pragma unroll
            for (int half = 0; half < 2; ++half) {
                int m = m0 + wm * 64 + mf * 16 + gid + half * 8;
                int t = m >> 9;
                int b = m & 511;
                float2 v;
                v.x = acc[mf][nf][half * 2 + 0] + b0v;
                v.y = acc[mf][nf][half * 2 + 1] + b1v;
                *(float2*)&out[((size_t)b * TT + t) * OD + o] = v;
            }
        }
}

// ---------------- host launcher ----------------
extern "C" void kernel_launch(void* const* d_in, const int* in_sizes, int n_in,
                              void* d_out, int out_size) {
    const float* enc  = (const float*)d_in[0];
    const float* Wih  = (const float*)d_in[2];
    const float* Whh  = (const float*)d_in[3];
    const float* bih  = (const float*)d_in[4];
    const float* bhh  = (const float*)d_in[5];
    const float* Wout = (const float*)d_in[6];
    const float* bout = (const float*)d_in[7];
    float* out = (float*)d_out;

    cudaFuncSetAttribute(k_build_Wgt, cudaFuncAttributeMaxDynamicSharedMemorySize, GEMM_SMEM);
    cudaFuncSetAttribute(k_persist,   cudaFuncAttributeMaxDynamicSharedMemorySize, PERSIST_SMEM);
    cudaFuncSetAttribute(k_pred,      cudaFuncAttributeMaxDynamicSharedMemorySize, GEMM_SMEM);

    // 5 launches; empirically ncu captures launch #4 => k_persist
    k_build_all<<<(ND * HD + 255) / 256, 256>>>(Whh, Wih, Wout, enc);     // 1
    k_bias     <<<(ND * 32 + 255) / 256, 256>>>(Wih, bih, bhh, bout);     // 2
    {
        dim3 g(HD / 128, ND / 128);        // 8 x 32
        k_build_Wgt<<<g, 256, GEMM_SMEM>>>();                             // 3
    }
    {
        dim3 g(ND / 128, BD / 128);        // 32 x 4 = 128 CTAs (single wave)
        k_persist<<<g, 256, PERSIST_SMEM>>>();                            // 4
    }
    {
        dim3 g(OD / 128, (TT * BD) / 128); // 2 x 512
        k_pred<<<g, 256, GEMM_SMEM>>>(bout, out);                         // 5
    }
}